// round 1
// baseline (speedup 1.0000x reference)
#include <cuda_runtime.h>
#include <cstdint>

// Problem constants
#define NN 8192
#define SS 3
#define DD 32
#define KSPLIT 2
#define BM 128
#define BK 32
#define KPER (NN / KSPLIT)

// Scratch (no cudaMalloc allowed)
__device__ float g_pre[SS * NN * DD];                 // pre[s][n][o], 3 MB
__device__ float g_part[SS * KSPLIT][NN * DD];        // partial sums, 6.3 MB

// ---------------------------------------------------------------------------
// Kernel 1: pre[s][n][o] = b[s][o] + sum_i x[n][i] * W[s][i][o]
// 256 threads = 8 rows x 32 cols per block, W/b/x staged in smem.
// ---------------------------------------------------------------------------
__global__ __launch_bounds__(256) void pre_kernel(const float* __restrict__ x,
                                                  const float* __restrict__ W,
                                                  const float* __restrict__ b) {
    __shared__ float sW[SS * DD * DD];
    __shared__ float sb[SS * DD];
    __shared__ float sx[8 * DD];

    int t = threadIdx.x;
    for (int i = t; i < SS * DD * DD; i += 256) sW[i] = W[i];
    if (t < SS * DD) sb[t] = b[t];
    sx[t] = x[blockIdx.x * 256 + t];
    __syncthreads();

    int col = t & 31;
    int rl  = t >> 5;
    int n   = blockIdx.x * 8 + rl;

#pragma unroll
    for (int s = 0; s < SS; s++) {
        float acc = sb[s * DD + col];
#pragma unroll
        for (int i = 0; i < DD; i++)
            acc = fmaf(sx[rl * DD + i], sW[(s * DD + i) * DD + col], acc);
        g_pre[(s * NN + n) * DD + col] = acc;
    }
}

// ---------------------------------------------------------------------------
// Kernel 2: partial[s*KSPLIT+z][m][o] = sum_{k in chunk} adj[s][m][k]*pre[s][k][o]
// Block: 128 threads. Warp = one 8-column group (cols cg*8..cg*8+7),
// lane = base row; thread computes rows {lane, lane+32, lane+64, lane+96}
// -> 4x8 outputs held as 4x4 packed f32x2 accumulators (FFMA2 path).
// sAdj padded +1 float/row: compute reads bank = (lane + k) % 32, conflict-free.
// sPre reads are warp-uniform -> broadcast, conflict-free.
// ---------------------------------------------------------------------------
__global__ __launch_bounds__(128) void gemm_kernel(const float* __restrict__ adj) {
    __shared__ float sAdj[BM * (BK + 1)];   // 128 x 33
    __shared__ float sPre[BK * DD];         // 32 x 32

    const int t    = threadIdx.x;
    const int lane = t & 31;
    const int cg   = t >> 5;                // warp id = column group
    const int m0   = blockIdx.x * BM;
    const int s    = blockIdx.y;
    const int k0   = blockIdx.z * KPER;

    const float* adjBase = adj + (size_t)(s * NN + m0) * NN + k0;
    const float* preBase = g_pre + ((size_t)s * NN + k0) * DD;

    unsigned long long acc[4][4];
#pragma unroll
    for (int i = 0; i < 4; i++)
#pragma unroll
        for (int j = 0; j < 4; j++) acc[i][j] = 0ULL;   // two packed +0.0f

    for (int kk = 0; kk < KPER; kk += BK) {
        // ---- load adj tile: 128 rows x 32 floats (coalesced LDG.128) ----
#pragma unroll
        for (int c = 0; c < 8; c++) {
            int idx = c * 512 + t * 4;          // linear float index in tile
            int row = idx >> 5;
            int k   = idx & 31;
            float4 v = *reinterpret_cast<const float4*>(adjBase + (size_t)row * NN + kk + k);
            float* d = &sAdj[row * (BK + 1) + k];
            d[0] = v.x; d[1] = v.y; d[2] = v.z; d[3] = v.w;
        }
        // ---- load pre tile: 32 rows x 32 floats, fully contiguous ----
#pragma unroll
        for (int c = 0; c < 2; c++) {
            int idx = c * 512 + t * 4;
            float4 v = *reinterpret_cast<const float4*>(preBase + (size_t)kk * DD + idx);
            *reinterpret_cast<float4*>(&sPre[idx]) = v;
        }
        __syncthreads();

#pragma unroll
        for (int k = 0; k < BK; k++) {
            unsigned long long p[4];
#pragma unroll
            for (int j = 0; j < 4; j++)
                p[j] = *reinterpret_cast<const unsigned long long*>(
                    &sPre[k * DD + cg * 8 + j * 2]);
#pragma unroll
            for (int i = 0; i < 4; i++) {
                float a = sAdj[(lane + 32 * i) * (BK + 1) + k];
                unsigned long long a2;
                unsigned int au = __float_as_uint(a);
                asm("mov.b64 %0, {%1, %1};" : "=l"(a2) : "r"(au));
#pragma unroll
                for (int j = 0; j < 4; j++)
                    asm("fma.rn.f32x2 %0, %1, %2, %0;"
                        : "+l"(acc[i][j]) : "l"(a2), "l"(p[j]));
            }
        }
        __syncthreads();
    }

    // ---- epilogue: deterministic partial-sum store (no atomics) ----
    float* po = g_part[s * KSPLIT + blockIdx.z];
#pragma unroll
    for (int i = 0; i < 4; i++) {
        int m = m0 + lane + 32 * i;
#pragma unroll
        for (int j = 0; j < 4; j++) {
            unsigned int lo, hi;
            asm("mov.b64 {%0, %1}, %2;" : "=r"(lo), "=r"(hi) : "l"(acc[i][j]));
            float2 v = make_float2(__uint_as_float(lo), __uint_as_float(hi));
            *reinterpret_cast<float2*>(&po[m * DD + cg * 8 + j * 2]) = v;
        }
    }
}

// ---------------------------------------------------------------------------
// Kernel 3: out = relu(sum over 6 partials)
// ---------------------------------------------------------------------------
__global__ __launch_bounds__(256) void reduce_kernel(float* __restrict__ out) {
    int i = blockIdx.x * 256 + threadIdx.x;
    float v = 0.0f;
#pragma unroll
    for (int p = 0; p < SS * KSPLIT; p++) v += g_part[p][i];
    out[i] = fmaxf(v, 0.0f);
}

// ---------------------------------------------------------------------------
// Launch: pre -> gemm (384 CTAs) -> reduce+relu
// ---------------------------------------------------------------------------
extern "C" void kernel_launch(void* const* d_in, const int* in_sizes, int n_in,
                              void* d_out, int out_size) {
    const float* x   = (const float*)d_in[0];   // [8192, 32]
    const float* adj = (const float*)d_in[1];   // [3, 8192, 8192]
    const float* W   = (const float*)d_in[2];   // [3, 32, 32]
    const float* b   = (const float*)d_in[3];   // [3, 32]
    float* out = (float*)d_out;                 // [8192, 32]

    pre_kernel<<<NN / 8, 256>>>(x, W, b);

    dim3 grid(NN / BM, SS, KSPLIT);             // 64 x 3 x 2 = 384 CTAs
    gemm_kernel<<<grid, 128>>>(adj);

    reduce_kernel<<<(NN * DD) / 256, 256>>>(out);
}

// round 5
// speedup vs baseline: 2.3514x; 2.3514x over previous
#include <cuda_runtime.h>
#include <cstdint>

// ---------------- problem / tiling constants ----------------
#define NN 8192
#define SS 3
#define DD 32
#define KSPLIT 8
#define KPER (NN / KSPLIT)            // 1024 K per item
#define BM 128
#define BK 64
#define SPI (KPER / BK)               // 16 stages per item
#define PADW 68                       // smem row stride in floats (16B-aligned, conflict-free)

// smem (uints): A double buf 2*128*68, B double buf 2*32*68
#define SA_STRIDE (BM * PADW)         // 8704
#define SB_STRIDE (DD * PADW)         // 2176
#define SB_BASE (2 * SA_STRIDE)       // 17408
#define SMEM_UINTS (SB_BASE + 2 * SB_STRIDE)   // 21760 -> 87040 B

// ---------------- scratch (no cudaMalloc allowed) ----------------
__device__ float g_preT[SS * DD * NN];            // preT[s][o][n], tf32-rounded, 3 MB
__device__ float g_part[SS * KSPLIT][NN * DD];    // K-split partials, 25 MB

// tf32 round-to-nearest: add into bit 12; HW truncates low 13 bits at the MMA.
__device__ __forceinline__ uint32_t tf32rn(uint32_t u) { return u + 0x1000u; }

// ---------------------------------------------------------------------------
// Kernel 1: preT[s][o][n] = rn_tf32( b[s][o] + sum_i x[n][i] * W[s][i][o] )
// ---------------------------------------------------------------------------
__global__ __launch_bounds__(256) void pre_kernel(const float* __restrict__ x,
                                                  const float* __restrict__ W,
                                                  const float* __restrict__ b) {
    __shared__ float sx[256 * 33];
    __shared__ float sW[DD * DD];
    __shared__ float sb[DD];

    int s = blockIdx.y;
    int n0 = blockIdx.x * 256;
    int t = threadIdx.x;

    for (int i = t; i < DD * DD; i += 256) sW[i] = W[s * DD * DD + i];
    if (t < DD) sb[t] = b[s * DD + t];
    for (int i = t; i < 256 * DD; i += 256) {
        int row = i >> 5, col = i & 31;
        sx[row * 33 + col] = x[(size_t)n0 * DD + i];
    }
    __syncthreads();

#pragma unroll
    for (int o = 0; o < DD; o++) {
        float acc = sb[o];
#pragma unroll
        for (int i = 0; i < DD; i++)
            acc = fmaf(sx[t * 33 + i], sW[i * DD + o], acc);
        uint32_t u = tf32rn(__float_as_uint(acc));
        g_preT[(size_t)(s * DD + o) * NN + n0 + t] = __uint_as_float(u);
    }
}

// ---------------------------------------------------------------------------
// Kernel 2: tf32 mma.sync GEMM
//   partial[s*KSPLIT+z][m][o] = sum_{k in chunk} adj[s][m][k] * pre[s][k][o]
// Block: 256 threads (8 warps x m16). BM=128, N=32 (4 n8 tiles), BK=64 stages,
// double-buffered smem. A rounded to tf32-rn at STS time; B pre-rounded.
// ---------------------------------------------------------------------------
__global__ void __launch_bounds__(256, 2) gemm_kernel(const float* __restrict__ adj) {
    extern __shared__ uint32_t smem[];

    const int t = threadIdx.x;
    const int wid = t >> 5, lane = t & 31;
    const int mt = blockIdx.x, s = blockIdx.y, z = blockIdx.z;

    const float* aB = adj + ((size_t)(s * NN + mt * BM)) * NN + (size_t)z * KPER;
    const float* bB = g_preT + (size_t)s * DD * NN + (size_t)z * KPER;

    // per-thread staging registers
    uint4 ra[8];
    uint4 rb[2];

    // A: 2048 float4/stage; thread does 8. row=idx>>4, c4=idx&15
    const int arow[1] = {0}; (void)arow;

    auto loadA = [&](int st) {
#pragma unroll
        for (int i = 0; i < 8; i++) {
            int idx = i * 256 + t;
            int row = idx >> 4, c4 = idx & 15;
            ra[i] = __ldcs(reinterpret_cast<const uint4*>(
                aB + (size_t)row * NN + st * BK + c4 * 4));
        }
    };
    auto loadB = [&](int st) {
#pragma unroll
        for (int j = 0; j < 2; j++) {
            int idx = j * 256 + t;
            int row = idx >> 4, c4 = idx & 15;
            rb[j] = *reinterpret_cast<const uint4*>(
                bB + (size_t)row * NN + st * BK + c4 * 4);
        }
    };
    auto stsAB = [&](int buf) {
        uint32_t* sA = smem + buf * SA_STRIDE;
        uint32_t* sB = smem + SB_BASE + buf * SB_STRIDE;
#pragma unroll
        for (int i = 0; i < 8; i++) {
            int idx = i * 256 + t;
            int row = idx >> 4, c4 = idx & 15;
            uint4 v = ra[i];
            v.x = tf32rn(v.x); v.y = tf32rn(v.y);
            v.z = tf32rn(v.z); v.w = tf32rn(v.w);
            *reinterpret_cast<uint4*>(&sA[row * PADW + c4 * 4]) = v;
        }
#pragma unroll
        for (int j = 0; j < 2; j++) {
            int idx = j * 256 + t;
            int row = idx >> 4, c4 = idx & 15;
            *reinterpret_cast<uint4*>(&sB[row * PADW + c4 * 4]) = rb[j];
        }
    };

    float acc[4][4];
#pragma unroll
    for (int nt = 0; nt < 4; nt++)
#pragma unroll
        for (int j = 0; j < 4; j++) acc[nt][j] = 0.0f;

    const int r = lane >> 2, c = lane & 3;
    const int m0w = wid * 16;

    auto compute = [&](int buf) {
        const uint32_t* sA = smem + buf * SA_STRIDE;
        const uint32_t* sB = smem + SB_BASE + buf * SB_STRIDE;
#pragma unroll
        for (int k8 = 0; k8 < BK / 8; k8++) {
            int k0 = k8 * 8;
            uint32_t a0 = sA[(m0w + r) * PADW + k0 + c];
            uint32_t a1 = sA[(m0w + r + 8) * PADW + k0 + c];
            uint32_t a2 = sA[(m0w + r) * PADW + k0 + c + 4];
            uint32_t a3 = sA[(m0w + r + 8) * PADW + k0 + c + 4];
#pragma unroll
            for (int nt = 0; nt < 4; nt++) {
                uint32_t b0 = sB[(nt * 8 + r) * PADW + k0 + c];
                uint32_t b1 = sB[(nt * 8 + r) * PADW + k0 + c + 4];
                asm volatile(
                    "mma.sync.aligned.m16n8k8.row.col.f32.tf32.tf32.f32 "
                    "{%0,%1,%2,%3}, {%4,%5,%6,%7}, {%8,%9}, {%0,%1,%2,%3};"
                    : "+f"(acc[nt][0]), "+f"(acc[nt][1]),
                      "+f"(acc[nt][2]), "+f"(acc[nt][3])
                    : "r"(a0), "r"(a1), "r"(a2), "r"(a3), "r"(b0), "r"(b1));
            }
        }
    };

    // ---- software pipeline ----
    loadA(0); loadB(0);
    stsAB(0);
    __syncthreads();

#pragma unroll 1
    for (int st = 0; st < SPI; st++) {
        if (st + 1 < SPI) { loadA(st + 1); loadB(st + 1); }
        compute(st & 1);
        __syncthreads();
        if (st + 1 < SPI) {
            stsAB((st + 1) & 1);
            __syncthreads();
        }
    }

    // ---- epilogue: deterministic partial store ----
    float* po = g_part[s * KSPLIT + z];
#pragma unroll
    for (int nt = 0; nt < 4; nt++) {
#pragma unroll
        for (int h = 0; h < 2; h++) {
            int m = mt * BM + m0w + r + 8 * h;
            float2 v = make_float2(acc[nt][2 * h], acc[nt][2 * h + 1]);
            *reinterpret_cast<float2*>(&po[(size_t)m * DD + nt * 8 + 2 * c]) = v;
        }
    }
}

// ---------------------------------------------------------------------------
// Kernel 3: out = relu(sum over 24 partials)
// ---------------------------------------------------------------------------
__global__ __launch_bounds__(256) void reduce_kernel(float* __restrict__ out) {
    int i = blockIdx.x * 256 + threadIdx.x;
    float4 a = make_float4(0.f, 0.f, 0.f, 0.f);
#pragma unroll
    for (int p = 0; p < SS * KSPLIT; p++) {
        float4 v = reinterpret_cast<const float4*>(g_part[p])[i];
        a.x += v.x; a.y += v.y; a.z += v.z; a.w += v.w;
    }
    a.x = fmaxf(a.x, 0.f); a.y = fmaxf(a.y, 0.f);
    a.z = fmaxf(a.z, 0.f); a.w = fmaxf(a.w, 0.f);
    reinterpret_cast<float4*>(out)[i] = a;
}

// ---------------------------------------------------------------------------
// Launch
// ---------------------------------------------------------------------------
extern "C" void kernel_launch(void* const* d_in, const int* in_sizes, int n_in,
                              void* d_out, int out_size) {
    const float* x   = (const float*)d_in[0];   // [8192, 32]
    const float* adj = (const float*)d_in[1];   // [3, 8192, 8192]
    const float* W   = (const float*)d_in[2];   // [3, 32, 32]
    const float* b   = (const float*)d_in[3];   // [3, 32]
    float* out = (float*)d_out;                 // [8192, 32]

    cudaFuncSetAttribute(gemm_kernel, cudaFuncAttributeMaxDynamicSharedMemorySize,
                         SMEM_UINTS * 4);

    pre_kernel<<<dim3(NN / 256, SS), 256>>>(x, W, b);
    gemm_kernel<<<dim3(NN / BM, SS, KSPLIT), 256, SMEM_UINTS * 4>>>(adj);
    reduce_kernel<<<(NN * DD / 4) / 256, 256>>>(out);
}

// round 6
// speedup vs baseline: 2.4620x; 1.0470x over previous
#include <cuda_runtime.h>
#include <cstdint>

// ---------------- problem / tiling constants ----------------
#define NN 8192
#define SS 3
#define DD 32
#define KSPLIT 8
#define KPER (NN / KSPLIT)            // 1024 K per item
#define BM 128
#define BK 32
#define SPI (KPER / BK)               // 32 stages per item
#define NSTAGES 4

// smem layout (in floats). Row stride 36: (36*r + c) % 32 = (4r + c) % 32 ->
// fragment reads conflict-free; 36 floats = 144B keeps 16B cp.async alignment.
#define SROW 36
#define SA_FLOATS (BM * SROW)                  // 4608
#define SB_FLOATS (DD * SROW)                  // 1152
#define ABASE 0
#define BBASE (NSTAGES * SA_FLOATS)            // 18432
#define SMEM_FLOATS (BBASE + NSTAGES * SB_FLOATS)   // 23040 -> 92160 B

// ---------------- scratch (no cudaMalloc allowed) ----------------
__device__ float g_preT[SS * DD * NN];            // preT[s][o][n], tf32-rn, 3 MB
__device__ float g_part[SS * KSPLIT][NN * DD];    // K-split partials, 25 MB

// tf32 round-to-nearest: +0x1000 into bit 12; MMA HW truncates low 13 bits.
__device__ __forceinline__ uint32_t tf32rn(uint32_t u) { return u + 0x1000u; }

// ---------------- cp.async helpers ----------------
__device__ __forceinline__ void cp16(uint32_t saddr, const float* g) {
    asm volatile("cp.async.cg.shared.global [%0], [%1], 16;"
                 :: "r"(saddr), "l"(g) : "memory");
}
__device__ __forceinline__ void cp_commit() {
    asm volatile("cp.async.commit_group;" ::: "memory");
}
__device__ __forceinline__ void cp_wait2() {
    asm volatile("cp.async.wait_group 2;" ::: "memory");
}

// ---------------------------------------------------------------------------
// Kernel 1: preT[s][o][n] = rn_tf32( b[s][o] + sum_i x[n][i] * W[s][i][o] )
// Block: 256 thr, 64 n-rows. thread: n_local = t&63, o in {oq*8 .. oq*8+7}.
// ---------------------------------------------------------------------------
__global__ __launch_bounds__(256) void pre_kernel(const float* __restrict__ x,
                                                  const float* __restrict__ W,
                                                  const float* __restrict__ b) {
    __shared__ float sx[64 * 33];
    __shared__ float sW[DD * DD];
    __shared__ float sb[DD];

    int s = blockIdx.y;
    int n0 = blockIdx.x * 64;
    int t = threadIdx.x;

    for (int i = t; i < DD * DD; i += 256) sW[i] = W[s * DD * DD + i];
    if (t < DD) sb[t] = b[s * DD + t];
    for (int i = t; i < 64 * DD; i += 256) {
        int row = i >> 5, col = i & 31;
        sx[row * 33 + col] = x[(size_t)n0 * DD + i];
    }
    __syncthreads();

    int nl = t & 63;
    int oq = t >> 6;                    // 0..3
#pragma unroll
    for (int j = 0; j < 8; j++) {
        int o = oq * 8 + j;
        float acc = sb[o];
#pragma unroll
        for (int i = 0; i < DD; i++)
            acc = fmaf(sx[nl * 33 + i], sW[i * DD + o], acc);
        uint32_t u = tf32rn(__float_as_uint(acc));
        g_preT[(size_t)(s * DD + o) * NN + n0 + nl] = __uint_as_float(u);
    }
}

// ---------------------------------------------------------------------------
// Kernel 2: tf32 mma.sync GEMM, cp.async 4-deep pipeline.
//   partial[s*KSPLIT+z][m][o] = sum_{k in chunk} adj[s][m][k]*pre[s][k][o]
// Block 256 thr = 8 warps x m16 rows; N=32 (4 n8 tiles); BK=32 per stage.
// A fragments get tf32-rn (+0x1000) after LDS; B is pre-rounded in pre_kernel.
// ---------------------------------------------------------------------------
__global__ void __launch_bounds__(256, 2) gemm_kernel(const float* __restrict__ adj) {
    extern __shared__ float smem[];
    const uint32_t sbase = (uint32_t)__cvta_generic_to_shared(smem);

    const int t = threadIdx.x;
    const int wid = t >> 5, lane = t & 31;
    const int mt = blockIdx.x, s = blockIdx.y, z = blockIdx.z;

    const float* aB = adj + ((size_t)(s * NN + mt * BM)) * NN + (size_t)z * KPER;
    const float* bB = g_preT + (size_t)s * DD * NN + (size_t)z * KPER;

    // cp.async mappings (16B granules)
    // A: 128 rows x 8 granules = 1024 granules -> 4 per thread
    // B: 32 rows x 8 granules = 256 granules  -> 1 per thread
    const int b_row = t >> 3, b_gr = t & 7;

    auto issue = [&](int st) {
        int buf = st & (NSTAGES - 1);
        uint32_t sa = sbase + (ABASE + buf * SA_FLOATS) * 4;
        uint32_t sb = sbase + (BBASE + buf * SB_FLOATS) * 4;
#pragma unroll
        for (int i = 0; i < 4; i++) {
            int idx = i * 256 + t;
            int row = idx >> 3, gr = idx & 7;
            cp16(sa + (row * SROW + gr * 4) * 4,
                 aB + (size_t)row * NN + st * BK + gr * 4);
        }
        cp16(sb + (b_row * SROW + b_gr * 4) * 4,
             bB + (size_t)b_row * NN + st * BK + b_gr * 4);
    };

    float acc[4][4];
#pragma unroll
    for (int nt = 0; nt < 4; nt++)
#pragma unroll
        for (int j = 0; j < 4; j++) acc[nt][j] = 0.0f;

    const int r = lane >> 2, c = lane & 3;
    const int m0w = wid * 16;

    auto compute = [&](int st) {
        int buf = st & (NSTAGES - 1);
        const uint32_t* sA = reinterpret_cast<const uint32_t*>(smem + ABASE + buf * SA_FLOATS);
        const uint32_t* sB = reinterpret_cast<const uint32_t*>(smem + BBASE + buf * SB_FLOATS);
#pragma unroll
        for (int k8 = 0; k8 < BK / 8; k8++) {
            int k0 = k8 * 8;
            uint32_t a0 = tf32rn(sA[(m0w + r) * SROW + k0 + c]);
            uint32_t a1 = tf32rn(sA[(m0w + r + 8) * SROW + k0 + c]);
            uint32_t a2 = tf32rn(sA[(m0w + r) * SROW + k0 + c + 4]);
            uint32_t a3 = tf32rn(sA[(m0w + r + 8) * SROW + k0 + c + 4]);
#pragma unroll
            for (int nt = 0; nt < 4; nt++) {
                uint32_t b0 = sB[(nt * 8 + r) * SROW + k0 + c];
                uint32_t b1 = sB[(nt * 8 + r) * SROW + k0 + c + 4];
                asm volatile(
                    "mma.sync.aligned.m16n8k8.row.col.f32.tf32.tf32.f32 "
                    "{%0,%1,%2,%3}, {%4,%5,%6,%7}, {%8,%9}, {%0,%1,%2,%3};"
                    : "+f"(acc[nt][0]), "+f"(acc[nt][1]),
                      "+f"(acc[nt][2]), "+f"(acc[nt][3])
                    : "r"(a0), "r"(a1), "r"(a2), "r"(a3), "r"(b0), "r"(b1));
            }
        }
    };

    // ---- pipeline: 3 stages in flight ahead of compute ----
    issue(0); cp_commit();
    issue(1); cp_commit();
    issue(2); cp_commit();

#pragma unroll 1
    for (int st = 0; st < SPI; st++) {
        cp_wait2();                 // oldest group (stage st) complete
        __syncthreads();            // visible to all warps
        compute(st);
        __syncthreads();            // buffer free before refill
        if (st + 3 < SPI) issue(st + 3);
        cp_commit();                // (possibly empty) keeps group count uniform
    }

    // ---- epilogue: deterministic partial store ----
    float* po = g_part[s * KSPLIT + z];
#pragma unroll
    for (int nt = 0; nt < 4; nt++) {
#pragma unroll
        for (int h = 0; h < 2; h++) {
            int m = mt * BM + m0w + r + 8 * h;
            float2 v = make_float2(acc[nt][2 * h], acc[nt][2 * h + 1]);
            *reinterpret_cast<float2*>(&po[(size_t)m * DD + nt * 8 + 2 * c]) = v;
        }
    }
}

// ---------------------------------------------------------------------------
// Kernel 3: out = relu(sum over 24 partials)
// ---------------------------------------------------------------------------
__global__ __launch_bounds__(256) void reduce_kernel(float* __restrict__ out) {
    int i = blockIdx.x * 256 + threadIdx.x;
    float4 a = make_float4(0.f, 0.f, 0.f, 0.f);
#pragma unroll
    for (int p = 0; p < SS * KSPLIT; p++) {
        float4 v = reinterpret_cast<const float4*>(g_part[p])[i];
        a.x += v.x; a.y += v.y; a.z += v.z; a.w += v.w;
    }
    a.x = fmaxf(a.x, 0.f); a.y = fmaxf(a.y, 0.f);
    a.z = fmaxf(a.z, 0.f); a.w = fmaxf(a.w, 0.f);
    reinterpret_cast<float4*>(out)[i] = a;
}

// ---------------------------------------------------------------------------
// Launch
// ---------------------------------------------------------------------------
extern "C" void kernel_launch(void* const* d_in, const int* in_sizes, int n_in,
                              void* d_out, int out_size) {
    const float* x   = (const float*)d_in[0];   // [8192, 32]
    const float* adj = (const float*)d_in[1];   // [3, 8192, 8192]
    const float* W   = (const float*)d_in[2];   // [3, 32, 32]
    const float* b   = (const float*)d_in[3];   // [3, 32]
    float* out = (float*)d_out;                 // [8192, 32]

    cudaFuncSetAttribute(gemm_kernel, cudaFuncAttributeMaxDynamicSharedMemorySize,
                         SMEM_FLOATS * 4);

    pre_kernel<<<dim3(NN / 64, SS), 256>>>(x, W, b);
    gemm_kernel<<<dim3(NN / BM, SS, KSPLIT), 256, SMEM_FLOATS * 4>>>(adj);
    reduce_kernel<<<(NN * DD / 4) / 256, 256>>>(out);
}